// round 16
// baseline (speedup 1.0000x reference)
#include <cuda_runtime.h>
#include <cuda_bf16.h>
#include <cuda_fp16.h>
#include <cstdint>

// Problem dims
#define BV   64
#define TT   500
#define FIN  1250
#define KP   1280          // FIN padded for B
#define HH   512
#define OO   2
#define MM   (BV * TT)     // 32000

// Neuron constants
#define DSYN  0.9048374180359595f
#define DREF  0.36787944117144233f
#define THETA 10.0f

// Scratch (device globals: allocation-free rule)
__device__ __align__(16) __half g_w1h[(size_t)HH * KP];  // 1.3 MB
__device__ __align__(16) __half g_u1 [(size_t)MM * HH];  // 32 MB (fp16)

// ---------------------------------------------------------------------------
// PTX helpers
// ---------------------------------------------------------------------------
__device__ __forceinline__ void ldsm_x4(uint32_t &r0, uint32_t &r1,
                                        uint32_t &r2, uint32_t &r3,
                                        uint32_t addr)
{
    asm volatile("ldmatrix.sync.aligned.m8n8.x4.shared.b16 {%0,%1,%2,%3}, [%4];"
                 : "=r"(r0), "=r"(r1), "=r"(r2), "=r"(r3) : "r"(addr));
}

// fp16-accumulator MMA: D(2 regs) = A(4) * B(2) + D
__device__ __forceinline__ void mma16816_f16(uint32_t* c, const uint32_t* a,
                                             const uint32_t b0, const uint32_t b1)
{
    asm volatile(
        "mma.sync.aligned.m16n8k16.row.col.f16.f16.f16.f16 "
        "{%0,%1}, {%2,%3,%4,%5}, {%6,%7}, {%0,%1};"
        : "+r"(c[0]), "+r"(c[1])
        : "r"(a[0]), "r"(a[1]), "r"(a[2]), "r"(a[3]), "r"(b0), "r"(b1));
}

__device__ __forceinline__ void cp_async16(uint32_t smem_addr, const void* gptr)
{
    asm volatile("cp.async.cg.shared.global [%0], [%1], 16;"
                 :: "r"(smem_addr), "l"(gptr));
}
__device__ __forceinline__ void cp_commit()
{
    asm volatile("cp.async.commit_group;");
}
__device__ __forceinline__ void cp_wait0()
{
    asm volatile("cp.async.wait_group 0;");
}

// ---------------------------------------------------------------------------
// K0: W1 fp32 -> fp16, pad K 1250 -> 1280 (L2-resident thereafter)
// ---------------------------------------------------------------------------
__global__ __launch_bounds__(256) void cvt_w1_kernel(
    const float* __restrict__ W, __half* __restrict__ Wh)
{
    long i = (long)blockIdx.x * blockDim.x + threadIdx.x;
    if (i >= (long)HH * KP) return;
    int  k = (int)(i % KP);
    long h = i / KP;
    float v = (k < FIN) ? W[h * FIN + k] : 0.0f;
    Wh[i] = __float2half(v);
}

// ---------------------------------------------------------------------------
// K1: U1[m,h] = sum_k X[m,k] * W1[h,k]   (fp16 HMMA, fp16 accum, fp16 out)
// R10-proven: BM=64, BN=256, BK=64, occ 2. 8 warps as 2(m) x 4(n),
// warp tile 32x64. A: fp32 LDG -> regs -> fp16 STS, one chunk ahead.
// B: cp.async dbl buffer. Rows padded to 72 halves (144B).
// ---------------------------------------------------------------------------
#define BM 64
#define BN 256
#define BK 64
#define LDA 72
#define ROWB (LDA * 2)             // 144 bytes/row
#define ABUFB (BM * ROWB)          // 9216
#define BBUFB (BN * ROWB)          // 36864
#define SMEM_GEMM (2 * ABUFB + 2 * BBUFB)   // 92160
#define NKCH (KP / BK)             // 20

__global__ __launch_bounds__(256, 2) void gemm1_mma_kernel(
    const float* __restrict__ X,
    const __half* __restrict__ Wh,
    __half* __restrict__ U)
{
    extern __shared__ __align__(16) char smem[];
    char* As = smem;
    char* Bs = smem + 2 * ABUFB;

    const int tid  = threadIdx.x;
    const int warp = tid >> 5;
    const int lane = tid & 31;
    const int wm   = warp >> 2;            // 0..1 -> m off wm*32
    const int wn   = warp & 3;             // 0..3 -> n off wn*64
    const int bm   = blockIdx.y * BM;
    const int bn   = blockIdx.x * BN;

    uint32_t acc[2][8][2];                 // fp16x2 accumulators
#pragma unroll
    for (int i = 0; i < 2; i++)
#pragma unroll
        for (int j = 0; j < 8; j++) {
            acc[i][j][0] = 0u;
            acc[i][j][1] = 0u;
        }

    const uint32_t asB = (uint32_t)__cvta_generic_to_shared(As);
    const uint32_t bsB = (uint32_t)__cvta_generic_to_shared(Bs);

    // A: 64 rows x 32 float2 = 2048 units, 8/thread. row=(tid>>5)+j*8, c2=tid&31
    const int aRowL = tid >> 5;
    const int aC2   = tid & 31;
    // B: 256 rows x 128B = 2048 x16B, 8/thread. row=(tid>>3)+j*32, g=tid&7
    const int bRowL = tid >> 3;
    const int bG    = tid & 7;

    const float* Xb = X + (size_t)bm * FIN;

    float2 pre[8];

    // ---- preload chunk 0
    {
#pragma unroll
        for (int j = 0; j < 8; j++) {
            int row = aRowL + j * 8;
            pre[j] = *(const float2*)(Xb + (size_t)row * FIN + aC2 * 2);
        }
#pragma unroll
        for (int j = 0; j < 8; j++) {
            int row = aRowL + j * 8;
            __half2 h2 = __float22half2_rn(pre[j]);
            *(__half2*)(As + row * ROWB + aC2 * 4) = h2;
        }
#pragma unroll
        for (int j = 0; j < 8; j++) {
            int row = bRowL + j * 32;
            cp_async16(bsB + (uint32_t)(row * ROWB + bG * 16),
                       Wh + (size_t)(bn + row) * KP + bG * 8);
        }
        cp_commit();
    }

    const uint32_t aRowOff = (uint32_t)(wm * 32 + (lane & 15));
    const uint32_t aColOff = (uint32_t)((lane >> 4) * 16);
    const uint32_t bRowOff = (uint32_t)(wn * 64 + ((lane >> 4) & 1) * 8 + (lane & 7));
    const uint32_t bColOff = (uint32_t)(((lane >> 3) & 1) * 16);

    for (int kt = 0; kt < NKCH; kt++) {
        cp_wait0();
        __syncthreads();                   // buffer kt&1 ready; nb free

        const int nb = (kt + 1) & 1;
        const bool more = (kt + 1 < NKCH);

        if (more) {
            const int kn = (kt + 1) * BK;
            if (kt + 1 < NKCH - 1) {
#pragma unroll
                for (int j = 0; j < 8; j++) {
                    int row = aRowL + j * 8;
                    pre[j] = *(const float2*)(Xb + (size_t)row * FIN + kn + aC2 * 2);
                }
            } else {                        // last chunk: k 1216..1279
#pragma unroll
                for (int j = 0; j < 8; j++) {
                    int row = aRowL + j * 8;
                    int k   = kn + aC2 * 2;
                    pre[j] = (k < FIN)
                        ? *(const float2*)(Xb + (size_t)row * FIN + k)
                        : make_float2(0.0f, 0.0f);
                }
            }
#pragma unroll
            for (int j = 0; j < 8; j++) {
                int row = bRowL + j * 32;
                cp_async16(bsB + (uint32_t)(nb * BBUFB + row * ROWB + bG * 16),
                           Wh + (size_t)(bn + row) * KP + kn + bG * 8);
            }
            cp_commit();
        } else {
            cp_commit();
        }

        const uint32_t aBase = asB + (uint32_t)((kt & 1) * ABUFB);
        const uint32_t bBase = bsB + (uint32_t)((kt & 1) * BBUFB);

#pragma unroll
        for (int ks = 0; ks < 4; ks++) {
            uint32_t a[2][4];
#pragma unroll
            for (int mt = 0; mt < 2; mt++) {
                uint32_t addr = aBase + (aRowOff + mt * 16) * ROWB
                                      + ks * 32 + aColOff;
                ldsm_x4(a[mt][0], a[mt][1], a[mt][2], a[mt][3], addr);
            }
            uint32_t b[4][4];
#pragma unroll
            for (int p = 0; p < 4; p++) {
                uint32_t addr = bBase + (bRowOff + p * 16) * ROWB
                                      + ks * 32 + bColOff;
                ldsm_x4(b[p][0], b[p][1], b[p][2], b[p][3], addr);
            }
#pragma unroll
            for (int mt = 0; mt < 2; mt++)
#pragma unroll
                for (int nt = 0; nt < 8; nt++)
                    mma16816_f16(acc[mt][nt], a[mt],
                                 b[nt >> 1][(nt & 1) * 2],
                                 b[nt >> 1][(nt & 1) * 2 + 1]);
        }

        if (more) {
#pragma unroll
            for (int j = 0; j < 8; j++) {
                int row = aRowL + j * 8;
                __half2 h2 = __float22half2_rn(pre[j]);
                *(__half2*)(As + nb * ABUFB + row * ROWB + aC2 * 4) = h2;
            }
        }
    }

    // epilogue: raw fp16x2 stores (frag reg0 -> row, reg1 -> row+8)
    const int cr = lane >> 2;
    const int cc = (lane & 3) * 2;
#pragma unroll
    for (int mt = 0; mt < 2; mt++) {
#pragma unroll
        for (int nt = 0; nt < 8; nt++) {
            int row0 = bm + wm * 32 + mt * 16 + cr;
            int col  = bn + wn * 64 + nt * 8 + cc;
            *(uint32_t*)(U + (size_t)row0 * HH + col)       = acc[mt][nt][0];
            *(uint32_t*)(U + (size_t)(row0 + 8) * HH + col) = acc[mt][nt][1];
        }
    }
}

// ---------------------------------------------------------------------------
// K2: FULLY FUSED tail: layer-1 PSP+spike scan + W2 projection (smem
// atomics) + layer-2 PSP+spike scan, all in one block per batch element.
// 512 threads = one per h chain; u2 lives in shared memory (4 KB);
// after syncthreads, threads 0-1 run the layer-2 recurrence inline.
// ---------------------------------------------------------------------------
#define SCH 20
#define SC2 20
__global__ __launch_bounds__(512) void scan_fused_kernel(
    const __half* __restrict__ U1, const float* __restrict__ W2,
    float* __restrict__ out)
{
    __shared__ float u2s[TT * OO];         // 4000 B
    const int b = blockIdx.x;
    const int h = threadIdx.x;             // 0..511

    // zero the smem accumulator
    for (int i = threadIdx.x; i < TT * OO; i += 512) u2s[i] = 0.0f;
    __syncthreads();

    // ---- layer-1 chain (per-h), projecting spikes into u2s via smem atomics
    {
        const __half* up = U1 + (size_t)b * TT * HH + h;
        const float w20 = W2[h];
        const float w21 = W2[HH + h];

        float b0[SCH], b1[SCH];
#pragma unroll
        for (int j = 0; j < SCH; j++) b0[j] = __half2float(up[(size_t)j * HH]);

        float p = 0.0f, r = 0.0f;
        const int NC = TT / SCH;           // 25 (odd)
        for (int c = 0; c < NC; c += 2) {
            if (c + 1 < NC) {
                const __half* nx = up + (size_t)(c + 1) * SCH * HH;
#pragma unroll
                for (int j = 0; j < SCH; j++) b1[j] = __half2float(nx[(size_t)j * HH]);
            }
#pragma unroll
            for (int j = 0; j < SCH; j++) {
                p = DSYN * p + b0[j];
                float v = p + r;
                if (v >= THETA) {
                    r = DREF * (r - 2.0f * THETA);
                    int t = c * SCH + j;
                    atomicAdd(&u2s[t * OO + 0], w20);
                    atomicAdd(&u2s[t * OO + 1], w21);
                } else {
                    r = DREF * r;
                }
            }
            if (c + 2 < NC) {
                const __half* nx = up + (size_t)(c + 2) * SCH * HH;
#pragma unroll
                for (int j = 0; j < SCH; j++) b0[j] = __half2float(nx[(size_t)j * HH]);
            }
            if (c + 1 < NC) {
#pragma unroll
                for (int j = 0; j < SCH; j++) {
                    p = DSYN * p + b1[j];
                    float v = p + r;
                    if (v >= THETA) {
                        r = DREF * (r - 2.0f * THETA);
                        int t = (c + 1) * SCH + j;
                        atomicAdd(&u2s[t * OO + 0], w20);
                        atomicAdd(&u2s[t * OO + 1], w21);
                    } else {
                        r = DREF * r;
                    }
                }
            }
        }
    }
    __syncthreads();

    // ---- layer-2 chain (threads 0-1), straight out of shared memory
    if (threadIdx.x < OO) {
        const int o = threadIdx.x;
        float*    op = out + (size_t)b * TT * OO + o;
        const float* usp = u2s + o;

        float b0[SC2], b1[SC2];
#pragma unroll
        for (int j = 0; j < SC2; j++) b0[j] = usp[j * OO];

        float p = 0.0f, r = 0.0f;
        const int NC = TT / SC2;           // 25 (odd)
        for (int c = 0; c < NC; c += 2) {
            if (c + 1 < NC) {
                const float* nx = usp + (c + 1) * SC2 * OO;
#pragma unroll
                for (int j = 0; j < SC2; j++) b1[j] = nx[j * OO];
            }
            {
                float* oo = op + (size_t)c * SC2 * OO;
#pragma unroll
                for (int j = 0; j < SC2; j++) {
                    p = DSYN * p + b0[j];
                    float v = p + r;
                    float s = (v >= THETA) ? 1.0f : 0.0f;
                    r = DREF * (r - 2.0f * THETA * s);
                    oo[(size_t)j * OO] = s;
                }
            }
            if (c + 2 < NC) {
                const float* nx = usp + (c + 2) * SC2 * OO;
#pragma unroll
                for (int j = 0; j < SC2; j++) b0[j] = nx[j * OO];
            }
            if (c + 1 < NC) {
                float* oo = op + (size_t)(c + 1) * SC2 * OO;
#pragma unroll
                for (int j = 0; j < SC2; j++) {
                    p = DSYN * p + b1[j];
                    float v = p + r;
                    float s = (v >= THETA) ? 1.0f : 0.0f;
                    r = DREF * (r - 2.0f * THETA * s);
                    oo[(size_t)j * OO] = s;
                }
            }
        }
    }
}

// ---------------------------------------------------------------------------
extern "C" void kernel_launch(void* const* d_in, const int* in_sizes, int n_in,
                              void* d_out, int out_size)
{
    const float* x  = (const float*)d_in[0];   // (64, 500, 1250)
    const float* W1 = (const float*)d_in[1];   // (512, 1250)
    const float* W2 = (const float*)d_in[2];   // (2, 512)
    float* out = (float*)d_out;                // (64, 500, 2)

    __half* w1h; cudaGetSymbolAddress((void**)&w1h, g_w1h);
    __half* u1;  cudaGetSymbolAddress((void**)&u1,  g_u1);

    {
        long n = (long)HH * KP;
        cvt_w1_kernel<<<(unsigned)((n + 255) / 256), 256>>>(W1, w1h);
    }

    cudaFuncSetAttribute(gemm1_mma_kernel,
                         cudaFuncAttributeMaxDynamicSharedMemorySize, SMEM_GEMM);
    dim3 g1(HH / BN, MM / BM);                // (2, 500)
    gemm1_mma_kernel<<<g1, 256, SMEM_GEMM>>>(x, w1h, u1);

    scan_fused_kernel<<<BV, 512>>>(u1, W2, out);
}